// round 1
// baseline (speedup 1.0000x reference)
#include <cuda_runtime.h>
#include <cuda_bf16.h>
#include <cuda_fp8.h>
#include <mma.h>

using namespace nvcuda;

#define KDIM 4096
#define K3   (3 * KDIM)      // packed K: [hi,hi,lo] x [hi,lo,hi]
#define MDIM 8192            // B*S = 4*2048
#define NDIM 4096

// Scratch operand buffers (device globals: allocation-free per harness rules)
__device__ __align__(128) __nv_bfloat16 g_A[(size_t)MDIM * K3];  // 192 MB
__device__ __align__(128) __nv_bfloat16 g_B[(size_t)NDIM * K3];  //  96 MB

// ---------------------------------------------------------------------------
// Quantize + hi/lo pack. One warp per group of 32 contiguous K elements.
// Matches reference bit-for-bit: scale = max(amax,1e-8)/448 (fp32 RN div),
// q = RNE-satfinite fp8_e4m3(x/scale), deq = float(q)*scale (fp32 RN mul).
// hi = bf16(deq), lo = bf16(deq - hi). Packed along K3:
//   A (dest=0): seg0=hi seg1=hi seg2=lo   (lo_seg=2)
//   B (dest=1): seg0=hi seg1=lo seg2=hi   (lo_seg=1)
// => sum over K3 = hiA*hiB + hiA*loB + loA*hiB  (loA*loB dropped, ~2^-18)
// ---------------------------------------------------------------------------
__global__ void quant_pack_kernel(const float* __restrict__ src, int rows,
                                  int lo_seg, int dest) {
    __nv_bfloat16* dst = dest ? g_B : g_A;
    int warps_per_block = blockDim.x >> 5;
    long long gid = (long long)blockIdx.x * warps_per_block + (threadIdx.x >> 5);
    int lane = threadIdx.x & 31;
    long long ngroups = (long long)rows * (KDIM / 32);
    if (gid >= ngroups) return;
    int row = (int)(gid >> 7);          // KDIM/32 = 128 groups per row
    int g   = (int)(gid & 127);
    int k   = g * 32 + lane;

    float v = src[(size_t)row * KDIM + k];
    float a = fabsf(v);
#pragma unroll
    for (int off = 16; off > 0; off >>= 1)
        a = fmaxf(a, __shfl_xor_sync(0xffffffffu, a, off));

    float scale = __fdiv_rn(fmaxf(a, 1e-8f), 448.0f);
    float q     = __fdiv_rn(v, scale);
    __nv_fp8_e4m3 f8(q);                        // RNE, satfinite
    float deq   = (float)f8 * scale;            // exact-ish dequant in fp32

    __nv_bfloat16 hi = __float2bfloat16(deq);
    __nv_bfloat16 lo = __float2bfloat16(deq - __bfloat162float(hi));

    size_t base = (size_t)row * K3;
#pragma unroll
    for (int s = 0; s < 3; s++)
        dst[base + (size_t)s * KDIM + k] = (s == lo_seg) ? lo : hi;
}

// ---------------------------------------------------------------------------
// WMMA bf16 GEMM: out[M,N] = Apack[M,K3] * Bpack[N,K3]^T + bias[N]
// Block tile 128x128, BK=32, 8 warps (2x4), warp tile 64x32 (4x2 wmma frags).
// ---------------------------------------------------------------------------
#define BM 128
#define BN 128
#define BK 32
#define LDS 40   // BK + 8 pad; 40 elems = 80B, multiple of 16B

__global__ void __launch_bounds__(256)
gemm_kernel(const float* __restrict__ bias, float* __restrict__ out) {
    __shared__ __align__(16) __nv_bfloat16 As[BM * LDS];
    __shared__ __align__(16) __nv_bfloat16 Bs[BN * LDS];
    __shared__ float staging[8][16 * 16];

    const int tid  = threadIdx.x;
    const int warp = tid >> 5;
    const int lane = tid & 31;
    const int wrow = warp >> 2;       // 0..1 -> 64-row slab
    const int wcol = warp & 3;        // 0..3 -> 32-col slab
    const int blockM = blockIdx.y * BM;
    const int blockN = blockIdx.x * BN;

    wmma::fragment<wmma::accumulator, 16, 16, 16, float> acc[4][2];
#pragma unroll
    for (int i = 0; i < 4; i++)
#pragma unroll
        for (int j = 0; j < 2; j++)
            wmma::fill_fragment(acc[i][j], 0.0f);

    const __nv_bfloat16* Abase = g_A + (size_t)blockM * K3;
    const __nv_bfloat16* Bbase = g_B + (size_t)blockN * K3;

    for (int kb = 0; kb < K3; kb += BK) {
        // Global -> shared: 128x32 bf16 per tile = 512 uint4 loads; 2/thread
#pragma unroll
        for (int it = 0; it < 2; it++) {
            int idx = tid + it * 256;       // 0..511
            int row = idx >> 2;             // 4 uint4 per 32-elem row
            int cv  = idx & 3;
            const uint4* sa = reinterpret_cast<const uint4*>(
                Abase + (size_t)row * K3 + kb + cv * 8);
            *reinterpret_cast<uint4*>(&As[row * LDS + cv * 8]) = *sa;
            const uint4* sb = reinterpret_cast<const uint4*>(
                Bbase + (size_t)row * K3 + kb + cv * 8);
            *reinterpret_cast<uint4*>(&Bs[row * LDS + cv * 8]) = *sb;
        }
        __syncthreads();

#pragma unroll
        for (int kk = 0; kk < BK; kk += 16) {
            wmma::fragment<wmma::matrix_a, 16, 16, 16, __nv_bfloat16,
                           wmma::row_major> afr[4];
            wmma::fragment<wmma::matrix_b, 16, 16, 16, __nv_bfloat16,
                           wmma::col_major> bfr[2];
#pragma unroll
            for (int i = 0; i < 4; i++)
                wmma::load_matrix_sync(afr[i],
                    &As[(wrow * 64 + i * 16) * LDS + kk], LDS);
#pragma unroll
            for (int j = 0; j < 2; j++)
                wmma::load_matrix_sync(bfr[j],
                    &Bs[(wcol * 32 + j * 16) * LDS + kk], LDS);
#pragma unroll
            for (int i = 0; i < 4; i++)
#pragma unroll
                for (int j = 0; j < 2; j++)
                    wmma::mma_sync(acc[i][j], afr[i], bfr[j], acc[i][j]);
        }
        __syncthreads();
    }

    // Epilogue: stage each 16x16 frag in shared, add bias, write fp32 out
#pragma unroll
    for (int i = 0; i < 4; i++) {
#pragma unroll
        for (int j = 0; j < 2; j++) {
            wmma::store_matrix_sync(staging[warp], acc[i][j], 16,
                                    wmma::mem_row_major);
            __syncwarp();
            int m0 = blockM + wrow * 64 + i * 16;
            int n0 = blockN + wcol * 32 + j * 16;
#pragma unroll
            for (int e = lane; e < 256; e += 32) {
                int r = e >> 4, c = e & 15;
                out[(size_t)(m0 + r) * NDIM + n0 + c] =
                    staging[warp][e] + bias[n0 + c];
            }
            __syncwarp();
        }
    }
}

// ---------------------------------------------------------------------------
extern "C" void kernel_launch(void* const* d_in, const int* in_sizes, int n_in,
                              void* d_out, int out_size) {
    const float* x    = (const float*)d_in[0];   // [4,2048,4096] fp32
    const float* W    = (const float*)d_in[1];   // [4096,4096]   fp32
    const float* bias = (const float*)d_in[2];   // [4096]        fp32
    float* out = (float*)d_out;                  // [8192,4096]   fp32

    {   // quantize + pack x -> g_A  (lo segment = 2)
        long long ngroups = (long long)MDIM * (KDIM / 32);
        int blocks = (int)((ngroups + 7) / 8);   // 8 warps / block
        quant_pack_kernel<<<blocks, 256>>>(x, MDIM, 2, 0);
    }
    {   // quantize + pack W -> g_B  (lo segment = 1)
        long long ngroups = (long long)NDIM * (KDIM / 32);
        int blocks = (int)((ngroups + 7) / 8);
        quant_pack_kernel<<<blocks, 256>>>(W, NDIM, 1, 1);
    }
    dim3 grid(NDIM / BN, MDIM / BM);   // 32 x 64
    gemm_kernel<<<grid, 256>>>(bias, out);
}

// round 8
// speedup vs baseline: 3.1161x; 3.1161x over previous
#include <cuda_runtime.h>
#include <cuda_fp16.h>
#include <cuda_fp8.h>
#include <cstdint>

#define KDIM 4096
#define MDIM 8192
#define NDIM 4096
#define NGRP 128              // K / 32 groups per row

#define BM 128
#define BN 128
#define BK 64                 // 2 groups per mainloop iter
#define STAGES 4
#define KSTEPS (KDIM / BK)    // 64
#define SA_OFF 32768
#define SB_OFF 33792
#define STAGE_BYTES 34816
#define SMEM_TOTAL (STAGES * STAGE_BYTES)

// Quantized operands + per-group scales (device globals, no allocation)
__device__ __align__(1024) __half g_qA[(size_t)MDIM * KDIM];   // 64 MB
__device__ __align__(1024) __half g_qB[(size_t)NDIM * KDIM];   // 32 MB
__device__ __align__(1024) float  g_sA[(size_t)MDIM * NGRP];   //  4 MB
__device__ __align__(1024) float  g_sB[(size_t)NDIM * NGRP];   //  2 MB

// ---------------------------------------------------------------------------
// PTX helpers (sm_80-portable only)
// ---------------------------------------------------------------------------
__device__ __forceinline__ uint32_t s2u(const void* p) {
    return (uint32_t)__cvta_generic_to_shared(p);
}
__device__ __forceinline__ void cp16(uint32_t s, const void* g) {
    asm volatile("cp.async.cg.shared.global [%0], [%1], 16;" :: "r"(s), "l"(g) : "memory");
}
__device__ __forceinline__ void cp8(uint32_t s, const void* g) {
    asm volatile("cp.async.ca.shared.global [%0], [%1], 8;" :: "r"(s), "l"(g) : "memory");
}
__device__ __forceinline__ void cp_commit() {
    asm volatile("cp.async.commit_group;" ::: "memory");
}
__device__ __forceinline__ void cp_wait2() {
    asm volatile("cp.async.wait_group 2;" ::: "memory");
}
__device__ __forceinline__ void ldsm4(uint32_t* r, uint32_t addr) {
    asm volatile("ldmatrix.sync.aligned.m8n8.x4.shared.b16 {%0,%1,%2,%3}, [%4];"
                 : "=r"(r[0]), "=r"(r[1]), "=r"(r[2]), "=r"(r[3]) : "r"(addr));
}
__device__ __forceinline__ void mma16816(float* d, const uint32_t* a,
                                         const uint32_t* b, const float* c) {
    asm volatile(
        "mma.sync.aligned.m16n8k16.row.col.f32.f16.f16.f32 "
        "{%0,%1,%2,%3}, {%4,%5,%6,%7}, {%8,%9}, {%10,%11,%12,%13};"
        : "=f"(d[0]), "=f"(d[1]), "=f"(d[2]), "=f"(d[3])
        : "r"(a[0]), "r"(a[1]), "r"(a[2]), "r"(a[3]), "r"(b[0]), "r"(b[1]),
          "f"(c[0]), "f"(c[1]), "f"(c[2]), "f"(c[3]));
}

// ---------------------------------------------------------------------------
// Quantize: q = fp8_e4m3(v / scale) stored EXACTLY as fp16; scale stored fp32.
// dest flag selects device-global buffers IN DEVICE CODE (host-side symbol
// addresses are invalid device pointers — the R2..R5 bug).
// One thread = 4 consecutive K (float4); 8-lane shuffle amax per 32-group.
// ---------------------------------------------------------------------------
__global__ void quant_kernel(const float* __restrict__ src, int dest) {
    __half* __restrict__ qdst = dest ? g_qB : g_qA;
    float*  __restrict__ sdst = dest ? g_sB : g_sA;

    long long t = (long long)blockIdx.x * blockDim.x + threadIdx.x;
    long long row = t >> 10;            // 1024 float4 per row
    int f4 = (int)(t & 1023);

    const float4 v4 = reinterpret_cast<const float4*>(src)[t];
    float a = fmaxf(fmaxf(fabsf(v4.x), fabsf(v4.y)),
                    fmaxf(fabsf(v4.z), fabsf(v4.w)));
    a = fmaxf(a, __shfl_xor_sync(0xffffffffu, a, 1));
    a = fmaxf(a, __shfl_xor_sync(0xffffffffu, a, 2));
    a = fmaxf(a, __shfl_xor_sync(0xffffffffu, a, 4));
    float scale = __fdiv_rn(fmaxf(a, 1e-8f), 448.0f);

    float vv[4] = {v4.x, v4.y, v4.z, v4.w};
    __half h[4];
#pragma unroll
    for (int i = 0; i < 4; i++) {
        float q = __fdiv_rn(vv[i], scale);
        __nv_fp8_e4m3 f8(q);                 // RNE, satfinite (matches reference)
        h[i] = __float2half((float)f8);      // exact: e4m3 subset of fp16
    }
    __half2 h01 = __halves2half2(h[0], h[1]);
    __half2 h23 = __halves2half2(h[2], h[3]);
    uint2 st;
    st.x = *reinterpret_cast<uint32_t*>(&h01);
    st.y = *reinterpret_cast<uint32_t*>(&h23);
    *reinterpret_cast<uint2*>(qdst + ((size_t)row << 12) + f4 * 4) = st;

    if ((f4 & 7) == 0)
        sdst[(size_t)row * NGRP + (f4 >> 3)] = scale;
}

// ---------------------------------------------------------------------------
// GEMM: out[M,N] = sum_g (qA_g . qB_g) * sA[m,g] * sB[n,g] + bias[n]
// 128x128 CTA tile, BK=64, 4-stage cp.async, 8 warps, warp tile 64x32.
// ---------------------------------------------------------------------------
__global__ void __launch_bounds__(256, 1)
gemm_kernel(const float* __restrict__ bias, float* __restrict__ out) {
    extern __shared__ __align__(1024) char smem_raw[];
    const uint32_t sbase = s2u(smem_raw);
    const int tid  = threadIdx.x;
    const int lane = tid & 31;
    const int warp = tid >> 5;
    const int warpM = warp & 1;          // 2 x 64 rows
    const int warpN = warp >> 1;         // 4 x 32 cols

    // Grid swizzle: 16-wide N super-columns so a wave is ~10x16 tiles
    const int gid = blockIdx.x;
    const int sc  = gid >> 10;
    const int rem = gid & 1023;
    const int blockN = ((sc << 4) | (rem & 15)) * BN;
    const int blockM = (rem >> 4) * BM;

    // Precomputed ldmatrix lane addressing
    const int lx7   = lane & 7;
    const int aRowB = warpM * 64 + (lane & 15);
    const int aCl   = lane >> 4;
    const int bRowB = warpN * 32 + ((lane >> 4) << 3) + (lane & 7);
    const int bCl   = (lane >> 3) & 1;
    const int rsIdx = warpM * 64 + (lane >> 2);
    const int csIdx = warpN * 32 + ((lane & 3) << 1);

    const __half* gA = g_qA + (size_t)blockM * KDIM;
    const __half* gB = g_qB + (size_t)blockN * KDIM;
    const float*  gsA = g_sA + (size_t)blockM * NGRP;
    const float*  gsB = g_sB + (size_t)blockN * NGRP;

    float acc[64];
#pragma unroll
    for (int i = 0; i < 64; i++) acc[i] = 0.0f;
    const float zf[4] = {0.f, 0.f, 0.f, 0.f};

    auto load_stage = [&](int stage, int kb) {
        uint32_t st = sbase + stage * STAGE_BYTES;
#pragma unroll
        for (int u = 0; u < 4; u++) {
            int idx = tid + u * 256;           // 0..1023 chunks
            int row = idx >> 3, c = idx & 7;
            cp16(st + row * 128 + (((c ^ (row & 7))) << 4),
                 gA + (size_t)row * KDIM + kb * 64 + c * 8);
        }
#pragma unroll
        for (int u = 0; u < 4; u++) {
            int idx = tid + u * 256;
            int row = idx >> 3, c = idx & 7;
            cp16(st + 16384 + row * 128 + (((c ^ (row & 7))) << 4),
                 gB + (size_t)row * KDIM + kb * 64 + c * 8);
        }
        if (tid < 128)
            cp8(st + SA_OFF + tid * 8, gsA + (size_t)tid * NGRP + kb * 2);
        else
            cp8(st + SB_OFF + (tid - 128) * 8,
                gsB + (size_t)(tid - 128) * NGRP + kb * 2);
    };

#pragma unroll
    for (int s = 0; s < 3; s++) { load_stage(s, s); cp_commit(); }

    for (int kb = 0; kb < KSTEPS; kb++) {
        cp_wait2();
        __syncthreads();
        const int stage = kb & 3;
        const uint32_t st = sbase + stage * STAGE_BYTES;
        const float2* sAf2 = reinterpret_cast<const float2*>(
            smem_raw + stage * STAGE_BYTES + SA_OFF);
        const float2* sBf2 = reinterpret_cast<const float2*>(
            smem_raw + stage * STAGE_BYTES + SB_OFF);

        float2 sLo[4], sHi[4], sC0[4], sC1[4];
#pragma unroll
        for (int i = 0; i < 4; i++) {
            sLo[i] = sAf2[rsIdx + i * 16];
            sHi[i] = sAf2[rsIdx + i * 16 + 8];
        }
#pragma unroll
        for (int j = 0; j < 4; j++) {
            sC0[j] = sBf2[csIdx + j * 8];
            sC1[j] = sBf2[csIdx + j * 8 + 1];
        }

#pragma unroll
        for (int g = 0; g < 2; g++) {
            uint32_t afr[2][4][4], bfr[2][2][4];
#pragma unroll
            for (int kh = 0; kh < 2; kh++) {
                const int kk = g * 2 + kh;
#pragma unroll
                for (int i = 0; i < 4; i++)
                    ldsm4(afr[kh][i],
                          st + (aRowB + i * 16) * 128 +
                              (((kk * 2 + aCl) ^ lx7) << 4));
#pragma unroll
                for (int jp = 0; jp < 2; jp++)
                    ldsm4(bfr[kh][jp],
                          st + 16384 + (bRowB + jp * 16) * 128 +
                              (((kk * 2 + bCl) ^ lx7) << 4));
            }
#pragma unroll
            for (int i = 0; i < 4; i++) {
                const float rlo = g ? sLo[i].y : sLo[i].x;
                const float rhi = g ? sHi[i].y : sHi[i].x;
#pragma unroll
                for (int j = 0; j < 4; j++) {
                    const float c0 = g ? sC0[j].y : sC0[j].x;
                    const float c1 = g ? sC1[j].y : sC1[j].x;
                    float t[4];
                    mma16816(t, afr[0][i], &bfr[0][j >> 1][(j & 1) * 2], zf);
                    mma16816(t, afr[1][i], &bfr[1][j >> 1][(j & 1) * 2], t);
                    float* A_ = &acc[((i << 2) + j) << 2];
                    A_[0] = fmaf(t[0], rlo * c0, A_[0]);
                    A_[1] = fmaf(t[1], rlo * c1, A_[1]);
                    A_[2] = fmaf(t[2], rhi * c0, A_[2]);
                    A_[3] = fmaf(t[3], rhi * c1, A_[3]);
                }
            }
        }
        if (kb < KSTEPS - 3) load_stage((kb + 3) & 3, kb + 3);
        cp_commit();   // empty-group commit keeps wait_group bookkeeping uniform
    }

    // Epilogue: bias add + fp32 store (float2 per fragment half)
#pragma unroll
    for (int i = 0; i < 4; i++) {
        const int r0 = blockM + warpM * 64 + i * 16 + (lane >> 2);
#pragma unroll
        for (int j = 0; j < 4; j++) {
            const int c = blockN + warpN * 32 + j * 8 + ((lane & 3) << 1);
            const float2 bb = __ldg(reinterpret_cast<const float2*>(bias + c));
            const float* A_ = &acc[((i << 2) + j) << 2];
            float2 v0 = {A_[0] + bb.x, A_[1] + bb.y};
            float2 v1 = {A_[2] + bb.x, A_[3] + bb.y};
            *reinterpret_cast<float2*>(out + (size_t)r0 * NDIM + c) = v0;
            *reinterpret_cast<float2*>(out + (size_t)(r0 + 8) * NDIM + c) = v1;
        }
    }
}

// ---------------------------------------------------------------------------
extern "C" void kernel_launch(void* const* d_in, const int* in_sizes, int n_in,
                              void* d_out, int out_size) {
    const float* x    = (const float*)d_in[0];   // [4,2048,4096] fp32
    const float* W    = (const float*)d_in[1];   // [4096,4096]   fp32
    const float* bias = (const float*)d_in[2];   // [4096]        fp32
    float* out = (float*)d_out;                  // [8192,4096]   fp32

    cudaFuncSetAttribute(gemm_kernel,
                         cudaFuncAttributeMaxDynamicSharedMemorySize, SMEM_TOTAL);

    quant_kernel<<<(MDIM * 1024) / 256, 256>>>(x, 0);   // -> g_qA, g_sA
    quant_kernel<<<(NDIM * 1024) / 256, 256>>>(W, 1);   // -> g_qB, g_sB
    gemm_kernel<<<(MDIM / BM) * (NDIM / BN), 256, SMEM_TOTAL>>>(bias, out);
}